// round 3
// baseline (speedup 1.0000x reference)
#include <cuda_runtime.h>
#include <math.h>
#include <stddef.h>

// Problem constants
#define BQ    512
#define SQ    199
#define DQ    512
#define SKMAX 300
#define TSLOTS 200

// GEMM tiling
#define BM 32
#define BN 64
#define BK 16
#define NTHR 128

// ---------------- scratch (device globals) ----------------
__device__ float g_rows[(size_t)BQ * SQ * DQ];   // skill_buf history [B][S][D]
__device__ float g_all [BQ * DQ];                // all_state
__device__ float g_lall[BQ * DQ];                // last_all (gated)
__device__ float g_lsk [BQ * DQ];                // last_sk  (gated)
__device__ float g_dot [BQ];                     // fused W_o2 dot accumulator
__device__ int   g_lt  [BQ * SKMAX];             // last_time

// precomputed static tables
__device__ float g_pre_gap  [TSLOTS * DQ];
__device__ float g_caf      [DQ];
__device__ float g_pre_o1   [SKMAX * DQ];
__device__ float g_pre_as_sk[SKMAX * DQ];
__device__ float g_pre_ss_sk[SKMAX * DQ];
__device__ float g_pre_as_an[2 * DQ];
__device__ float g_pre_ss_an[2 * DQ];

__device__ __forceinline__ float sigf(float z) { return 1.f / (1.f + expf(-z)); }

// packed f32x2 helpers
__device__ __forceinline__ void ffma2(unsigned long long& d, unsigned long long a, unsigned long long b) {
    asm("fma.rn.f32x2 %0, %1, %2, %0;" : "+l"(d) : "l"(a), "l"(b));
}
__device__ __forceinline__ unsigned long long dup2(float x) {
    unsigned long long r; asm("mov.b64 %0, {%1, %1};" : "=l"(r) : "f"(x)); return r;
}
__device__ __forceinline__ float2 unpk2(unsigned long long v) {
    float2 r; asm("mov.b64 {%0, %1}, %2;" : "=f"(r.x), "=f"(r.y) : "l"(v)); return r;
}

// ---------------- init ----------------
__global__ void k_init_state(const float* __restrict__ ls_state) {
    int b = blockIdx.x;
    for (int j = threadIdx.x; j < DQ; j += blockDim.x) g_all[b * DQ + j] = ls_state[j];
    for (int k = threadIdx.x; k < SKMAX; k += blockDim.x) g_lt[b * SKMAX + k] = 0;
    if (threadIdx.x == 0) g_dot[b] = 0.f;
}

__global__ void k_init_rows(const float* __restrict__ s0) {
    int t = blockIdx.x, b = blockIdx.y;
    size_t o = ((size_t)b * SQ + t) * DQ;
    for (int j = threadIdx.x; j < DQ; j += blockDim.x) g_rows[o + j] = s0[t * DQ + j];
}

// ---------------- precompute static tables ----------------
__global__ void k_pre(const float* __restrict__ skill_embed, const float* __restrict__ ans_embed,
                      const float* __restrict__ time_embed,
                      const float* __restrict__ W_sf, const float* __restrict__ b_sf,
                      const float* __restrict__ W_af, const float* __restrict__ b_af,
                      const float* __restrict__ W_ss, const float* __restrict__ b_ss,
                      const float* __restrict__ W_as, const float* __restrict__ b_as,
                      const float* __restrict__ W_o1, const float* __restrict__ b_o1) {
    __shared__ float s_src[DQ];
    int r = blockIdx.x;
    const float* src; const float* W; const float* bias; float* out;
    if (r < 200)       { src = time_embed + r * DQ;            W = W_sf + DQ * DQ;     bias = b_sf; out = g_pre_gap + r * DQ; }
    else if (r == 200) { src = time_embed + DQ;                W = W_af + DQ * DQ;     bias = b_af; out = g_caf; }
    else if (r < 501)  { int k = r - 201;  src = skill_embed + k * DQ; W = W_o1 + 2 * DQ * DQ; bias = b_o1; out = g_pre_o1 + k * DQ; }
    else if (r < 801)  { int k = r - 501;  src = skill_embed + k * DQ; W = W_as + DQ * DQ;     bias = b_as; out = g_pre_as_sk + k * DQ; }
    else if (r < 803)  { int a = r - 801;  src = ans_embed + a * DQ;   W = W_as + DQ * DQ;     bias = 0;    out = g_pre_as_an + a * DQ; }
    else if (r < 1103) { int k = r - 803;  src = skill_embed + k * DQ; W = W_ss + DQ * DQ;     bias = b_ss; out = g_pre_ss_sk + k * DQ; }
    else               { int a = r - 1103; src = ans_embed + a * DQ;   W = W_ss + DQ * DQ;     bias = 0;    out = g_pre_ss_an + a * DQ; }
    for (int i = threadIdx.x; i < DQ; i += blockDim.x) s_src[i] = src[i];
    __syncthreads();
    for (int j = threadIdx.x; j < DQ; j += blockDim.x) {
        float acc = bias ? bias[j] : 0.f;
        #pragma unroll 8
        for (int i = 0; i < DQ; i++) acc += s_src[i] * W[i * DQ + j];
        out[j] = acc;
    }
}

// ---------------- stage A: gates ----------------
// nt 0..7  : f_sk  (A = gathered history row, W_sf top)  -> g_lsk
// nt 8..15 : f_all (A = all_state,            W_af top)  -> g_lall
__global__ void __launch_bounds__(NTHR)
k_stageA(int s, const int* __restrict__ nsk,
         const float* __restrict__ W_sf, const float* __restrict__ W_af) {
    __shared__ const float* s_rowp[BM];
    __shared__ int s_gap[BM];
    __shared__ __align__(16) float As[2][BK][BM + 2];
    __shared__ __align__(16) float Bs[2][BK][BN];

    const int nt = blockIdx.x, mt = blockIdx.y;
    const bool sf = (nt < 8);
    const int n0 = (nt & 7) * BN, m0 = mt * BM;
    const int tid = threadIdx.x;

    if (tid < BM) {
        int b = m0 + tid;
        if (sf) {
            int k = nsk[b * SQ + s];
            int t = g_lt[b * SKMAX + k];
            s_rowp[tid] = g_rows + ((size_t)b * SQ + t) * DQ;
            s_gap[tid] = s - t;
        } else {
            s_rowp[tid] = g_all + b * DQ;
        }
    }
    __syncthreads();

    const int am = tid >> 2, akq = (tid & 3) * 4;
    const int br = tid >> 3, bc = (tid & 7) * 8;
    const int tx = tid & 7, ty = tid >> 3;

    const float* aptr = s_rowp[am] + akq;
    const float* bptr = (sf ? W_sf : W_af) + n0 + br * DQ + bc;

    // prologue
    {
        float4 av  = *(const float4*)aptr;
        float4 bv0 = *(const float4*)bptr;
        float4 bv1 = *(const float4*)(bptr + 4);
        As[0][akq + 0][am] = av.x; As[0][akq + 1][am] = av.y;
        As[0][akq + 2][am] = av.z; As[0][akq + 3][am] = av.w;
        *(float4*)&Bs[0][br][bc] = bv0;
        *(float4*)&Bs[0][br][bc + 4] = bv1;
    }
    __syncthreads();

    unsigned long long acc0[4] = {0,0,0,0}, acc1[4] = {0,0,0,0};
    const int NK = DQ / BK;  // 32
    for (int kc = 0; kc < NK; kc++) {
        const int cur = kc & 1;
        const bool more = (kc + 1 < NK);
        float4 nav, nbv0, nbv1;
        if (more) {
            int k0 = (kc + 1) * BK;
            nav  = *(const float4*)(aptr + k0);
            nbv0 = *(const float4*)(bptr + (size_t)k0 * DQ);
            nbv1 = *(const float4*)(bptr + (size_t)k0 * DQ + 4);
        }
        #pragma unroll
        for (int kk = 0; kk < BK; kk++) {
            float2 a2 = *(const float2*)&As[cur][kk][ty * 2];
            unsigned long long pa0 = dup2(a2.x), pa1 = dup2(a2.y);
            ulonglong2 b01 = *(const ulonglong2*)&Bs[cur][kk][tx * 8];
            ulonglong2 b23 = *(const ulonglong2*)&Bs[cur][kk][tx * 8 + 4];
            ffma2(acc0[0], pa0, b01.x); ffma2(acc0[1], pa0, b01.y);
            ffma2(acc0[2], pa0, b23.x); ffma2(acc0[3], pa0, b23.y);
            ffma2(acc1[0], pa1, b01.x); ffma2(acc1[1], pa1, b01.y);
            ffma2(acc1[2], pa1, b23.x); ffma2(acc1[3], pa1, b23.y);
        }
        if (more) {
            int nx = cur ^ 1;
            As[nx][akq + 0][am] = nav.x; As[nx][akq + 1][am] = nav.y;
            As[nx][akq + 2][am] = nav.z; As[nx][akq + 3][am] = nav.w;
            *(float4*)&Bs[nx][br][bc] = nbv0;
            *(float4*)&Bs[nx][br][bc + 4] = nbv1;
        }
        __syncthreads();
    }

    float* outp = sf ? g_lsk : g_lall;
    const int cb = n0 + tx * 8;
    #pragma unroll
    for (int i = 0; i < 2; i++) {
        int m = ty * 2 + i;
        int b = m0 + m;
        const float* xr = s_rowp[m] + cb;
        const float* prep = (sf ? g_pre_gap + (size_t)s_gap[m] * DQ : g_caf) + cb;
        const unsigned long long* acc = i ? acc1 : acc0;
        float4 xv0 = *(const float4*)xr,        xv1 = *(const float4*)(xr + 4);
        float4 pv0 = *(const float4*)prep,      pv1 = *(const float4*)(prep + 4);
        float2 z0 = unpk2(acc[0]), z1 = unpk2(acc[1]), z2 = unpk2(acc[2]), z3 = unpk2(acc[3]);
        float4 o0, o1;
        o0.x = xv0.x * sigf(z0.x + pv0.x); o0.y = xv0.y * sigf(z0.y + pv0.y);
        o0.z = xv0.z * sigf(z1.x + pv0.z); o0.w = xv0.w * sigf(z1.y + pv0.w);
        o1.x = xv1.x * sigf(z2.x + pv1.x); o1.y = xv1.y * sigf(z2.y + pv1.y);
        o1.z = xv1.z * sigf(z3.x + pv1.z); o1.w = xv1.w * sigf(z3.y + pv1.w);
        *(float4*)&outp[(size_t)b * DQ + cb] = o0;
        *(float4*)&outp[(size_t)b * DQ + cb + 4] = o1;
    }
}

// ---------------- stage B ----------------
// nt 0..7  : relu hidden + fused W_o2 dot -> atomicAdd g_dot     (K=1024)
// nt 8..15 : new_all = lall + tanh(...)   -> g_all               (K=512)
// nt 16..23: new_sk  = lsk  + tanh(...)   -> g_rows[:,s,:]       (K=512)
__global__ void __launch_bounds__(NTHR)
k_stageB(int s, const int* __restrict__ nsk, const int* __restrict__ nans,
         const float* __restrict__ W_o1, const float* __restrict__ W_as,
         const float* __restrict__ W_ss, const float* __restrict__ W_o2) {
    __shared__ __align__(16) float As[2][BK][BM + 2];
    __shared__ __align__(16) float Bs[2][BK][BN];

    const int nt = blockIdx.x, mt = blockIdx.y;
    const int region = nt >> 3;
    const int n0 = (nt & 7) * BN, m0 = mt * BM;
    const int tid = threadIdx.x;
    const int am = tid >> 2, akq = (tid & 3) * 4;
    const int br = tid >> 3, bc = (tid & 7) * 8;
    const int tx = tid & 7, ty = tid >> 3;

    const float* Wbase = (region == 0) ? W_o1 : (region == 1) ? W_as : W_ss;
    const float* bptr = Wbase + n0 + br * DQ + bc;
    const int NK = (region == 0) ? (2 * DQ / BK) : (DQ / BK);
    const float* Abase = (region == 2) ? g_lsk : g_lall;
    const size_t rowoff = (size_t)(m0 + am) * DQ + akq;

    auto aSrc = [&](int k0) -> const float* {
        if (region == 0 && k0 >= DQ) return g_lsk + rowoff + (k0 - DQ);
        return Abase + rowoff + k0;
    };

    {
        float4 av  = *(const float4*)aSrc(0);
        float4 bv0 = *(const float4*)bptr;
        float4 bv1 = *(const float4*)(bptr + 4);
        As[0][akq + 0][am] = av.x; As[0][akq + 1][am] = av.y;
        As[0][akq + 2][am] = av.z; As[0][akq + 3][am] = av.w;
        *(float4*)&Bs[0][br][bc] = bv0;
        *(float4*)&Bs[0][br][bc + 4] = bv1;
    }
    __syncthreads();

    unsigned long long acc0[4] = {0,0,0,0}, acc1[4] = {0,0,0,0};
    for (int kc = 0; kc < NK; kc++) {
        const int cur = kc & 1;
        const bool more = (kc + 1 < NK);
        float4 nav, nbv0, nbv1;
        if (more) {
            int k0 = (kc + 1) * BK;
            nav  = *(const float4*)aSrc(k0);
            nbv0 = *(const float4*)(bptr + (size_t)k0 * DQ);
            nbv1 = *(const float4*)(bptr + (size_t)k0 * DQ + 4);
        }
        #pragma unroll
        for (int kk = 0; kk < BK; kk++) {
            float2 a2 = *(const float2*)&As[cur][kk][ty * 2];
            unsigned long long pa0 = dup2(a2.x), pa1 = dup2(a2.y);
            ulonglong2 b01 = *(const ulonglong2*)&Bs[cur][kk][tx * 8];
            ulonglong2 b23 = *(const ulonglong2*)&Bs[cur][kk][tx * 8 + 4];
            ffma2(acc0[0], pa0, b01.x); ffma2(acc0[1], pa0, b01.y);
            ffma2(acc0[2], pa0, b23.x); ffma2(acc0[3], pa0, b23.y);
            ffma2(acc1[0], pa1, b01.x); ffma2(acc1[1], pa1, b01.y);
            ffma2(acc1[2], pa1, b23.x); ffma2(acc1[3], pa1, b23.y);
        }
        if (more) {
            int nx = cur ^ 1;
            As[nx][akq + 0][am] = nav.x; As[nx][akq + 1][am] = nav.y;
            As[nx][akq + 2][am] = nav.z; As[nx][akq + 3][am] = nav.w;
            *(float4*)&Bs[nx][br][bc] = nbv0;
            *(float4*)&Bs[nx][br][bc + 4] = nbv1;
        }
        __syncthreads();
    }

    const int cb = n0 + tx * 8;
    #pragma unroll
    for (int i = 0; i < 2; i++) {
        int m = ty * 2 + i;
        int b = m0 + m;
        int ks = nsk[b * SQ + s];
        const unsigned long long* acc = i ? acc1 : acc0;
        float2 z0 = unpk2(acc[0]), z1 = unpk2(acc[1]), z2 = unpk2(acc[2]), z3 = unpk2(acc[3]);
        float z[8] = {z0.x, z0.y, z1.x, z1.y, z2.x, z2.y, z3.x, z3.y};
        if (region == 0) {
            const float* prep = g_pre_o1 + (size_t)ks * DQ + cb;
            const float* wo2 = W_o2 + cb;
            float4 p0 = *(const float4*)prep, p1 = *(const float4*)(prep + 4);
            float4 w0 = *(const float4*)wo2,  w1 = *(const float4*)(wo2 + 4);
            float pp[8] = {p0.x,p0.y,p0.z,p0.w,p1.x,p1.y,p1.z,p1.w};
            float ww[8] = {w0.x,w0.y,w0.z,w0.w,w1.x,w1.y,w1.z,w1.w};
            float part = 0.f;
            #pragma unroll
            for (int j = 0; j < 8; j++) part += fmaxf(z[j] + pp[j], 0.f) * ww[j];
            part += __shfl_xor_sync(0xffffffffu, part, 1);
            part += __shfl_xor_sync(0xffffffffu, part, 2);
            part += __shfl_xor_sync(0xffffffffu, part, 4);
            if (tx == 0) atomicAdd(&g_dot[b], part);
        } else if (region == 1) {
            int a = nans[b * SQ + s];
            const float* p1 = g_pre_as_sk + (size_t)ks * DQ + cb;
            const float* p2 = g_pre_as_an + (size_t)a * DQ + cb;
            const float* lr = g_lall + (size_t)b * DQ + cb;
            float4 q0 = *(const float4*)p1, q1 = *(const float4*)(p1 + 4);
            float4 r0 = *(const float4*)p2, r1 = *(const float4*)(p2 + 4);
            float4 l0 = *(const float4*)lr, l1 = *(const float4*)(lr + 4);
            float4 o0, o1;
            o0.x = l0.x + tanhf(z[0] + q0.x + r0.x); o0.y = l0.y + tanhf(z[1] + q0.y + r0.y);
            o0.z = l0.z + tanhf(z[2] + q0.z + r0.z); o0.w = l0.w + tanhf(z[3] + q0.w + r0.w);
            o1.x = l1.x + tanhf(z[4] + q1.x + r1.x); o1.y = l1.y + tanhf(z[5] + q1.y + r1.y);
            o1.z = l1.z + tanhf(z[6] + q1.z + r1.z); o1.w = l1.w + tanhf(z[7] + q1.w + r1.w);
            *(float4*)&g_all[(size_t)b * DQ + cb] = o0;
            *(float4*)&g_all[(size_t)b * DQ + cb + 4] = o1;
        } else {
            int a = nans[b * SQ + s];
            const float* p1 = g_pre_ss_sk + (size_t)ks * DQ + cb;
            const float* p2 = g_pre_ss_an + (size_t)a * DQ + cb;
            const float* lr = g_lsk + (size_t)b * DQ + cb;
            float4 q0 = *(const float4*)p1, q1 = *(const float4*)(p1 + 4);
            float4 r0 = *(const float4*)p2, r1 = *(const float4*)(p2 + 4);
            float4 l0 = *(const float4*)lr, l1 = *(const float4*)(lr + 4);
            float4 o0, o1;
            o0.x = l0.x + tanhf(z[0] + q0.x + r0.x); o0.y = l0.y + tanhf(z[1] + q0.y + r0.y);
            o0.z = l0.z + tanhf(z[2] + q0.z + r0.z); o0.w = l0.w + tanhf(z[3] + q0.w + r0.w);
            o1.x = l1.x + tanhf(z[4] + q1.x + r1.x); o1.y = l1.y + tanhf(z[5] + q1.y + r1.y);
            o1.z = l1.z + tanhf(z[6] + q1.z + r1.z); o1.w = l1.w + tanhf(z[7] + q1.w + r1.w);
            size_t o = ((size_t)b * SQ + s) * DQ + cb;
            *(float4*)&g_rows[o] = o0;
            *(float4*)&g_rows[o + 4] = o1;
        }
    }
}

// ---------------- stage C: tiny finisher ----------------
__global__ void k_stageC(int s, const int* __restrict__ nsk,
                         const float* __restrict__ b_o2, float* __restrict__ P) {
    int b = threadIdx.x + blockIdx.x * blockDim.x;
    if (b < BQ) {
        P[b * SQ + s] = sigf(g_dot[b] + b_o2[0]);
        g_lt[b * SKMAX + nsk[b * SQ + s]] = s;
        g_dot[b] = 0.f;   // ready for next step
    }
}

// ---------------- launch ----------------
extern "C" void kernel_launch(void* const* d_in, const int* in_sizes, int n_in,
                              void* d_out, int out_size) {
    const int*   nsk          = (const int*)d_in[4];
    const int*   nans         = (const int*)d_in[5];
    const float* skill_embed  = (const float*)d_in[6];
    const float* ans_embed    = (const float*)d_in[7];
    const float* time_embed   = (const float*)d_in[8];
    const float* ls_state     = (const float*)d_in[9];
    const float* skill_state0 = (const float*)d_in[10];
    const float* W_sf = (const float*)d_in[11]; const float* b_sf = (const float*)d_in[12];
    const float* W_af = (const float*)d_in[13]; const float* b_af = (const float*)d_in[14];
    const float* W_ss = (const float*)d_in[15]; const float* b_ss = (const float*)d_in[16];
    const float* W_as = (const float*)d_in[17]; const float* b_as = (const float*)d_in[18];
    const float* W_o1 = (const float*)d_in[19]; const float* b_o1 = (const float*)d_in[20];
    const float* W_o2 = (const float*)d_in[21]; const float* b_o2 = (const float*)d_in[22];
    float* P = (float*)d_out;

    k_init_rows<<<dim3(SQ, BQ), 256>>>(skill_state0);
    k_init_state<<<BQ, 256>>>(ls_state);
    k_pre<<<1105, 256>>>(skill_embed, ans_embed, time_embed,
                         W_sf, b_sf, W_af, b_af, W_ss, b_ss, W_as, b_as, W_o1, b_o1);

    for (int s = 0; s < SQ; s++) {
        k_stageA<<<dim3(16, 16), NTHR>>>(s, nsk, W_sf, W_af);
        k_stageB<<<dim3(24, 16), NTHR>>>(s, nsk, nans, W_o1, W_as, W_ss, W_o2);
        k_stageC<<<1, BQ>>>(s, nsk, b_o2, P);
    }
}

// round 7
// speedup vs baseline: 1.1844x; 1.1844x over previous
#include <cuda_runtime.h>
#include <math.h>
#include <stddef.h>

// Problem constants
#define BQ    512
#define SQ    199
#define DQ    512
#define SKMAX 300
#define TSLOTS 200

// GEMM tiling (R1 envelope: 256 threads, 64x64 tile, BK=16, double buffer)
#define BM 64
#define BN 64
#define BK 16

// ---------------- scratch (device globals) ----------------
__device__ float g_rows[(size_t)BQ * SQ * DQ];   // skill_buf history [B][S][D]
__device__ float g_all [BQ * DQ];                // all_state
__device__ float g_lall[BQ * DQ];                // last_all (gated)
__device__ float g_lsk [BQ * DQ];                // last_sk  (gated)
__device__ float g_h   [BQ * DQ];                // relu hidden
__device__ int   g_lt  [BQ * SKMAX];             // last_time

// precomputed static tables
__device__ float g_pre_gap  [TSLOTS * DQ];
__device__ float g_caf      [DQ];
__device__ float g_pre_o1   [SKMAX * DQ];
__device__ float g_pre_as_sk[SKMAX * DQ];
__device__ float g_pre_ss_sk[SKMAX * DQ];
__device__ float g_pre_as_an[2 * DQ];
__device__ float g_pre_ss_an[2 * DQ];

__device__ __forceinline__ float sigf(float z) { return 1.f / (1.f + expf(-z)); }

// packed f32x2 FMA (FFMA2)
__device__ __forceinline__ void ffma2(unsigned long long& d, unsigned long long a, unsigned long long b) {
    asm("fma.rn.f32x2 %0, %1, %2, %0;" : "+l"(d) : "l"(a), "l"(b));
}
__device__ __forceinline__ float2 unpk2(unsigned long long v) {
    float2 r; asm("mov.b64 {%0, %1}, %2;" : "=f"(r.x), "=f"(r.y) : "l"(v)); return r;
}

// ---------------- init ----------------
__global__ void k_init_state(const float* __restrict__ ls_state) {
    int b = blockIdx.x;
    for (int j = threadIdx.x; j < DQ; j += blockDim.x) g_all[b * DQ + j] = ls_state[j];
    for (int k = threadIdx.x; k < SKMAX; k += blockDim.x) g_lt[b * SKMAX + k] = 0;
}

__global__ void k_init_rows(const float* __restrict__ s0) {
    int t = blockIdx.x, b = blockIdx.y;
    size_t o = ((size_t)b * SQ + t) * DQ;
    for (int j = threadIdx.x; j < DQ; j += blockDim.x) g_rows[o + j] = s0[t * DQ + j];
}

// ---------------- precompute static tables ----------------
__global__ void k_pre(const float* __restrict__ skill_embed, const float* __restrict__ ans_embed,
                      const float* __restrict__ time_embed,
                      const float* __restrict__ W_sf, const float* __restrict__ b_sf,
                      const float* __restrict__ W_af, const float* __restrict__ b_af,
                      const float* __restrict__ W_ss, const float* __restrict__ b_ss,
                      const float* __restrict__ W_as, const float* __restrict__ b_as,
                      const float* __restrict__ W_o1, const float* __restrict__ b_o1) {
    __shared__ float s_src[DQ];
    int r = blockIdx.x;
    const float* src; const float* W; const float* bias; float* out;
    if (r < 200)       { src = time_embed + r * DQ;            W = W_sf + DQ * DQ;     bias = b_sf; out = g_pre_gap + r * DQ; }
    else if (r == 200) { src = time_embed + DQ;                W = W_af + DQ * DQ;     bias = b_af; out = g_caf; }
    else if (r < 501)  { int k = r - 201;  src = skill_embed + k * DQ; W = W_o1 + 2 * DQ * DQ; bias = b_o1; out = g_pre_o1 + k * DQ; }
    else if (r < 801)  { int k = r - 501;  src = skill_embed + k * DQ; W = W_as + DQ * DQ;     bias = b_as; out = g_pre_as_sk + k * DQ; }
    else if (r < 803)  { int a = r - 801;  src = ans_embed + a * DQ;   W = W_as + DQ * DQ;     bias = 0;    out = g_pre_as_an + a * DQ; }
    else if (r < 1103) { int k = r - 803;  src = skill_embed + k * DQ; W = W_ss + DQ * DQ;     bias = b_ss; out = g_pre_ss_sk + k * DQ; }
    else               { int a = r - 1103; src = ans_embed + a * DQ;   W = W_ss + DQ * DQ;     bias = 0;    out = g_pre_ss_an + a * DQ; }
    for (int i = threadIdx.x; i < DQ; i += blockDim.x) s_src[i] = src[i];
    __syncthreads();
    for (int j = threadIdx.x; j < DQ; j += blockDim.x) {
        float acc = bias ? bias[j] : 0.f;
        #pragma unroll 8
        for (int i = 0; i < DQ; i++) acc += s_src[i] * W[i * DQ + j];
        out[j] = acc;
    }
}

// ---------------- stage A: gates ----------------
// nt 0..7  : f_sk  (A = gathered history row, W_sf top)  -> g_lsk
// nt 8..15 : f_all (A = all_state,            W_af top)  -> g_lall
__global__ void __launch_bounds__(256)
k_stageA(int s, const int* __restrict__ nsk,
         const float* __restrict__ W_sf, const float* __restrict__ W_af) {
    __shared__ const float* s_rowp[BM];
    __shared__ int s_gap[BM];
    __shared__ __align__(16) float As[2][BK][2 * BM];   // A duplicated: (a,a) pairs
    __shared__ __align__(16) float Bs[2][BK][BN];

    const int nt = blockIdx.x, mt = blockIdx.y;
    const bool sf = (nt < 8);
    const int n0 = (nt & 7) * BN, m0 = mt * BM;
    const int tid = threadIdx.x;

    if (tid < BM) {
        int b = m0 + tid;
        if (sf) {
            int k = nsk[b * SQ + s];
            int t = g_lt[b * SKMAX + k];
            s_rowp[tid] = g_rows + ((size_t)b * SQ + t) * DQ;
            s_gap[tid] = s - t;
        } else {
            s_rowp[tid] = g_all + b * DQ;
        }
    }
    __syncthreads();

    const int am = tid >> 2, akq = (tid & 3) * 4;   // loader: row am, k-quad akq
    const int bk = tid >> 4, bjq = (tid & 15) * 4;  // loader: k-row bk, col-quad bjq
    const int tx = tid & 15, ty = tid >> 4;         // compute: 4 cols x2, 4 rows

    const float* aptr = s_rowp[am] + akq;
    const float* bptr = (sf ? W_sf : W_af) + n0 + bk * DQ + bjq;

    // prologue
    {
        float4 av = *(const float4*)aptr;
        float4 bv = *(const float4*)bptr;
        float2 d;
        d.x = d.y = av.x; *(float2*)&As[0][akq + 0][2 * am] = d;
        d.x = d.y = av.y; *(float2*)&As[0][akq + 1][2 * am] = d;
        d.x = d.y = av.z; *(float2*)&As[0][akq + 2][2 * am] = d;
        d.x = d.y = av.w; *(float2*)&As[0][akq + 3][2 * am] = d;
        *(float4*)&Bs[0][bk][bjq] = bv;
    }
    __syncthreads();

    unsigned long long acc[4][2] = {};
    const int NK = DQ / BK;  // 32
    for (int kc = 0; kc < NK; kc++) {
        const int cur = kc & 1;
        const bool more = (kc + 1 < NK);
        float4 nav, nbv;
        if (more) {
            int k0 = (kc + 1) * BK;
            nav = *(const float4*)(aptr + k0);
            nbv = *(const float4*)(bptr + (size_t)k0 * DQ);
        }
        #pragma unroll
        for (int kk = 0; kk < BK; kk++) {
            ulonglong2 a01 = *(const ulonglong2*)&As[cur][kk][ty * 8];
            ulonglong2 a23 = *(const ulonglong2*)&As[cur][kk][ty * 8 + 4];
            ulonglong2 b   = *(const ulonglong2*)&Bs[cur][kk][tx * 4];
            ffma2(acc[0][0], a01.x, b.x); ffma2(acc[0][1], a01.x, b.y);
            ffma2(acc[1][0], a01.y, b.x); ffma2(acc[1][1], a01.y, b.y);
            ffma2(acc[2][0], a23.x, b.x); ffma2(acc[2][1], a23.x, b.y);
            ffma2(acc[3][0], a23.y, b.x); ffma2(acc[3][1], a23.y, b.y);
        }
        if (more) {
            int nx = cur ^ 1;
            float2 d;
            d.x = d.y = nav.x; *(float2*)&As[nx][akq + 0][2 * am] = d;
            d.x = d.y = nav.y; *(float2*)&As[nx][akq + 1][2 * am] = d;
            d.x = d.y = nav.z; *(float2*)&As[nx][akq + 2][2 * am] = d;
            d.x = d.y = nav.w; *(float2*)&As[nx][akq + 3][2 * am] = d;
            *(float4*)&Bs[nx][bk][bjq] = nbv;
        }
        __syncthreads();
    }

    float* outp = sf ? g_lsk : g_lall;
    const int cb = n0 + tx * 4;
    #pragma unroll
    for (int i = 0; i < 4; i++) {
        int m = ty * 4 + i;
        int b = m0 + m;
        const float* xr = s_rowp[m] + cb;
        const float* prep = (sf ? g_pre_gap + (size_t)s_gap[m] * DQ : g_caf) + cb;
        float2 z0 = unpk2(acc[i][0]), z1 = unpk2(acc[i][1]);
        float4 xv = *(const float4*)xr;
        float4 pv = *(const float4*)prep;
        float4 o;
        o.x = xv.x * sigf(z0.x + pv.x);
        o.y = xv.y * sigf(z0.y + pv.y);
        o.z = xv.z * sigf(z1.x + pv.z);
        o.w = xv.w * sigf(z1.y + pv.w);
        *(float4*)&outp[(size_t)b * DQ + cb] = o;
    }
}

// ---------------- stage B ----------------
// nt 0..7  : h = relu([lall|lsk] @ W_o1[0:2d] + pre_o1)   -> g_h    (K=1024)
// nt 8..15 : new_all = lall + tanh(...)                   -> g_all  (K=512)
// nt 16..23: new_sk  = lsk  + tanh(...)                   -> g_rows (K=512)
__global__ void __launch_bounds__(256)
k_stageB(int s, const int* __restrict__ nsk, const int* __restrict__ nans,
         const float* __restrict__ W_o1, const float* __restrict__ W_as,
         const float* __restrict__ W_ss) {
    __shared__ __align__(16) float As[2][BK][2 * BM];
    __shared__ __align__(16) float Bs[2][BK][BN];

    const int nt = blockIdx.x, mt = blockIdx.y;
    const int region = nt >> 3;
    const int n0 = (nt & 7) * BN, m0 = mt * BM;
    const int tid = threadIdx.x;
    const int am = tid >> 2, akq = (tid & 3) * 4;
    const int bk = tid >> 4, bjq = (tid & 15) * 4;
    const int tx = tid & 15, ty = tid >> 4;

    const float* Wbase = (region == 0) ? W_o1 : (region == 1) ? W_as : W_ss;
    const float* bptr = Wbase + n0 + bk * DQ + bjq;
    const int NK = (region == 0) ? (2 * DQ / BK) : (DQ / BK);
    const float* Abase = (region == 2) ? g_lsk : g_lall;
    const size_t rowoff = (size_t)(m0 + am) * DQ + akq;

    auto aSrc = [&](int k0) -> const float* {
        if (region == 0 && k0 >= DQ) return g_lsk + rowoff + (k0 - DQ);
        return Abase + rowoff + k0;
    };

    {
        float4 av = *(const float4*)aSrc(0);
        float4 bv = *(const float4*)bptr;
        float2 d;
        d.x = d.y = av.x; *(float2*)&As[0][akq + 0][2 * am] = d;
        d.x = d.y = av.y; *(float2*)&As[0][akq + 1][2 * am] = d;
        d.x = d.y = av.z; *(float2*)&As[0][akq + 2][2 * am] = d;
        d.x = d.y = av.w; *(float2*)&As[0][akq + 3][2 * am] = d;
        *(float4*)&Bs[0][bk][bjq] = bv;
    }
    __syncthreads();

    unsigned long long acc[4][2] = {};
    for (int kc = 0; kc < NK; kc++) {
        const int cur = kc & 1;
        const bool more = (kc + 1 < NK);
        float4 nav, nbv;
        if (more) {
            int k0 = (kc + 1) * BK;
            nav = *(const float4*)aSrc(k0);
            nbv = *(const float4*)(bptr + (size_t)k0 * DQ);
        }
        #pragma unroll
        for (int kk = 0; kk < BK; kk++) {
            ulonglong2 a01 = *(const ulonglong2*)&As[cur][kk][ty * 8];
            ulonglong2 a23 = *(const ulonglong2*)&As[cur][kk][ty * 8 + 4];
            ulonglong2 b   = *(const ulonglong2*)&Bs[cur][kk][tx * 4];
            ffma2(acc[0][0], a01.x, b.x); ffma2(acc[0][1], a01.x, b.y);
            ffma2(acc[1][0], a01.y, b.x); ffma2(acc[1][1], a01.y, b.y);
            ffma2(acc[2][0], a23.x, b.x); ffma2(acc[2][1], a23.x, b.y);
            ffma2(acc[3][0], a23.y, b.x); ffma2(acc[3][1], a23.y, b.y);
        }
        if (more) {
            int nx = cur ^ 1;
            float2 d;
            d.x = d.y = nav.x; *(float2*)&As[nx][akq + 0][2 * am] = d;
            d.x = d.y = nav.y; *(float2*)&As[nx][akq + 1][2 * am] = d;
            d.x = d.y = nav.z; *(float2*)&As[nx][akq + 2][2 * am] = d;
            d.x = d.y = nav.w; *(float2*)&As[nx][akq + 3][2 * am] = d;
            *(float4*)&Bs[nx][bk][bjq] = nbv;
        }
        __syncthreads();
    }

    const int cb = n0 + tx * 4;
    #pragma unroll
    for (int i = 0; i < 4; i++) {
        int m = ty * 4 + i;
        int b = m0 + m;
        int ks = nsk[b * SQ + s];
        float2 z0 = unpk2(acc[i][0]), z1 = unpk2(acc[i][1]);
        float z[4] = {z0.x, z0.y, z1.x, z1.y};
        if (region == 0) {
            const float* prep = g_pre_o1 + (size_t)ks * DQ + cb;
            float4 pv = *(const float4*)prep;
            float4 o;
            o.x = fmaxf(z[0] + pv.x, 0.f);
            o.y = fmaxf(z[1] + pv.y, 0.f);
            o.z = fmaxf(z[2] + pv.z, 0.f);
            o.w = fmaxf(z[3] + pv.w, 0.f);
            *(float4*)&g_h[(size_t)b * DQ + cb] = o;
        } else if (region == 1) {
            int a = nans[b * SQ + s];
            float4 q = *(const float4*)(g_pre_as_sk + (size_t)ks * DQ + cb);
            float4 r = *(const float4*)(g_pre_as_an + (size_t)a * DQ + cb);
            float4 l = *(const float4*)(g_lall + (size_t)b * DQ + cb);
            float4 o;
            o.x = l.x + tanhf(z[0] + q.x + r.x);
            o.y = l.y + tanhf(z[1] + q.y + r.y);
            o.z = l.z + tanhf(z[2] + q.z + r.z);
            o.w = l.w + tanhf(z[3] + q.w + r.w);
            *(float4*)&g_all[(size_t)b * DQ + cb] = o;
        } else {
            int a = nans[b * SQ + s];
            float4 q = *(const float4*)(g_pre_ss_sk + (size_t)ks * DQ + cb);
            float4 r = *(const float4*)(g_pre_ss_an + (size_t)a * DQ + cb);
            float4 l = *(const float4*)(g_lsk + (size_t)b * DQ + cb);
            float4 o;
            o.x = l.x + tanhf(z[0] + q.x + r.x);
            o.y = l.y + tanhf(z[1] + q.y + r.y);
            o.z = l.z + tanhf(z[2] + q.z + r.z);
            o.w = l.w + tanhf(z[3] + q.w + r.w);
            *(float4*)&g_rows[((size_t)b * SQ + s) * DQ + cb] = o;
        }
    }
}

// ---------------- stage C: output prob + last_time update ----------------
__global__ void k_stageC(int s, const int* __restrict__ nsk,
                         const float* __restrict__ W_o2, const float* __restrict__ b_o2,
                         float* __restrict__ P) {
    int warp = (blockIdx.x * blockDim.x + threadIdx.x) >> 5;  // 0..127
    int lane = threadIdx.x & 31;
    for (int b = warp; b < BQ; b += 128) {
        float acc = 0.f;
        for (int j = lane; j < DQ; j += 32) acc += g_h[b * DQ + j] * W_o2[j];
        #pragma unroll
        for (int off = 16; off; off >>= 1) acc += __shfl_xor_sync(0xffffffffu, acc, off);
        if (lane == 0) {
            P[b * SQ + s] = sigf(acc + b_o2[0]);
            g_lt[b * SKMAX + nsk[b * SQ + s]] = s;
        }
    }
}

// ---------------- launch ----------------
extern "C" void kernel_launch(void* const* d_in, const int* in_sizes, int n_in,
                              void* d_out, int out_size) {
    const int*   nsk          = (const int*)d_in[4];
    const int*   nans         = (const int*)d_in[5];
    const float* skill_embed  = (const float*)d_in[6];
    const float* ans_embed    = (const float*)d_in[7];
    const float* time_embed   = (const float*)d_in[8];
    const float* ls_state     = (const float*)d_in[9];
    const float* skill_state0 = (const float*)d_in[10];
    const float* W_sf = (const float*)d_in[11]; const float* b_sf = (const float*)d_in[12];
    const float* W_af = (const float*)d_in[13]; const float* b_af = (const float*)d_in[14];
    const float* W_ss = (const float*)d_in[15]; const float* b_ss = (const float*)d_in[16];
    const float* W_as = (const float*)d_in[17]; const float* b_as = (const float*)d_in[18];
    const float* W_o1 = (const float*)d_in[19]; const float* b_o1 = (const float*)d_in[20];
    const float* W_o2 = (const float*)d_in[21]; const float* b_o2 = (const float*)d_in[22];
    float* P = (float*)d_out;

    k_init_rows<<<dim3(SQ, BQ), 256>>>(skill_state0);
    k_init_state<<<BQ, 256>>>(ls_state);
    k_pre<<<1105, 256>>>(skill_embed, ans_embed, time_embed,
                         W_sf, b_sf, W_af, b_af, W_ss, b_ss, W_as, b_as, W_o1, b_o1);

    for (int s = 0; s < SQ; s++) {
        k_stageA<<<dim3(16, 8), 256>>>(s, nsk, W_sf, W_af);
        k_stageB<<<dim3(24, 8), 256>>>(s, nsk, nans, W_o1, W_as, W_ss);
        k_stageC<<<16, 256>>>(s, nsk, W_o2, b_o2, P);
    }
}

// round 12
// speedup vs baseline: 1.4696x; 1.2408x over previous
#include <cuda_runtime.h>
#include <math.h>
#include <stddef.h>

// Problem constants
#define BQ    512
#define SQ    199
#define DQ    512
#define SKMAX 300
#define TSLOTS 200

// GEMM tiling: 256 threads, 64x64 tile, BK=32, double buffer
#define BM 64
#define BN 64
#define BK 32

// ---------------- scratch (device globals) ----------------
__device__ float g_rows[(size_t)BQ * SQ * DQ];   // skill_buf history [B][S][D]
__device__ float g_all [BQ * DQ];                // all_state
__device__ float g_lall[BQ * DQ];                // last_all (gated)
__device__ float g_lsk [BQ * DQ];                // last_sk  (gated)
__device__ float g_h   [BQ * DQ];                // relu hidden
__device__ int   g_lt  [BQ * SKMAX];             // last_time

// precomputed static tables
__device__ float g_pre_gap  [TSLOTS * DQ];
__device__ float g_caf      [DQ];
__device__ float g_pre_o1   [SKMAX * DQ];
__device__ float g_pre_as_sk[SKMAX * DQ];
__device__ float g_pre_ss_sk[SKMAX * DQ];
__device__ float g_pre_as_an[2 * DQ];
__device__ float g_pre_ss_an[2 * DQ];

__device__ __forceinline__ float sigf(float z) { return 1.f / (1.f + expf(-z)); }

// ---------------- init ----------------
__global__ void k_init_state(const float* __restrict__ ls_state) {
    int b = blockIdx.x;
    for (int j = threadIdx.x; j < DQ; j += blockDim.x) g_all[b * DQ + j] = ls_state[j];
    for (int k = threadIdx.x; k < SKMAX; k += blockDim.x) g_lt[b * SKMAX + k] = 0;
}

__global__ void k_init_rows(const float* __restrict__ s0) {
    int t = blockIdx.x, b = blockIdx.y;
    size_t o = ((size_t)b * SQ + t) * DQ;
    for (int j = threadIdx.x; j < DQ; j += blockDim.x) g_rows[o + j] = s0[t * DQ + j];
}

// ---------------- precompute static tables ----------------
__global__ void k_pre(const float* __restrict__ skill_embed, const float* __restrict__ ans_embed,
                      const float* __restrict__ time_embed,
                      const float* __restrict__ W_sf, const float* __restrict__ b_sf,
                      const float* __restrict__ W_af, const float* __restrict__ b_af,
                      const float* __restrict__ W_ss, const float* __restrict__ b_ss,
                      const float* __restrict__ W_as, const float* __restrict__ b_as,
                      const float* __restrict__ W_o1, const float* __restrict__ b_o1) {
    __shared__ float s_src[DQ];
    int r = blockIdx.x;
    const float* src; const float* W; const float* bias; float* out;
    if (r < 200)       { src = time_embed + r * DQ;            W = W_sf + DQ * DQ;     bias = b_sf; out = g_pre_gap + r * DQ; }
    else if (r == 200) { src = time_embed + DQ;                W = W_af + DQ * DQ;     bias = b_af; out = g_caf; }
    else if (r < 501)  { int k = r - 201;  src = skill_embed + k * DQ; W = W_o1 + 2 * DQ * DQ; bias = b_o1; out = g_pre_o1 + k * DQ; }
    else if (r < 801)  { int k = r - 501;  src = skill_embed + k * DQ; W = W_as + DQ * DQ;     bias = b_as; out = g_pre_as_sk + k * DQ; }
    else if (r < 803)  { int a = r - 801;  src = ans_embed + a * DQ;   W = W_as + DQ * DQ;     bias = 0;    out = g_pre_as_an + a * DQ; }
    else if (r < 1103) { int k = r - 803;  src = skill_embed + k * DQ; W = W_ss + DQ * DQ;     bias = b_ss; out = g_pre_ss_sk + k * DQ; }
    else               { int a = r - 1103; src = ans_embed + a * DQ;   W = W_ss + DQ * DQ;     bias = 0;    out = g_pre_ss_an + a * DQ; }
    for (int i = threadIdx.x; i < DQ; i += blockDim.x) s_src[i] = src[i];
    __syncthreads();
    for (int j = threadIdx.x; j < DQ; j += blockDim.x) {
        float acc = bias ? bias[j] : 0.f;
        #pragma unroll 8
        for (int i = 0; i < DQ; i++) acc += s_src[i] * W[i * DQ + j];
        out[j] = acc;
    }
}

// ---------------- stage A: gates ----------------
// nt 0..7  : f_sk  (A = gathered history row, W_sf top)  -> g_lsk
// nt 8..15 : f_all (A = all_state,            W_af top)  -> g_lall
__global__ void __launch_bounds__(256, 1)
k_stageA(int s, const int* __restrict__ nsk,
         const float* __restrict__ W_sf, const float* __restrict__ W_af) {
    __shared__ const float* s_rowp[BM];
    __shared__ int s_gap[BM];
    __shared__ __align__(16) float As[2][BK][BM];
    __shared__ __align__(16) float Bs[2][BK][BN];

    const int nt = blockIdx.x, mt = blockIdx.y;
    const bool sf = (nt < 8);
    const int n0 = (nt & 7) * BN, m0 = mt * BM;
    const int tid = threadIdx.x;

    if (tid < BM) {
        int b = m0 + tid;
        if (sf) {
            int k = nsk[b * SQ + s];
            int t = g_lt[b * SKMAX + k];
            s_rowp[tid] = g_rows + ((size_t)b * SQ + t) * DQ;
            s_gap[tid] = s - t;
        } else {
            s_rowp[tid] = g_all + b * DQ;
        }
    }
    __syncthreads();

    // loaders: A tile 64x32 -> thread: row am, 8 consecutive k at akq
    //          B tile 32x64 -> thread: k-row bk, 8 consecutive cols at bjq
    const int am = tid >> 2, akq = (tid & 3) * 8;
    const int bk = tid >> 3, bjq = (tid & 7) * 8;
    const int tx = tid & 15, ty = tid >> 4;         // compute: 4 cols, 4 rows

    const float* aptr = s_rowp[am] + akq;
    const float* bptr = (sf ? W_sf : W_af) + n0 + bk * DQ + bjq;

    // prologue
    {
        float4 a0 = *(const float4*)(aptr);
        float4 a1 = *(const float4*)(aptr + 4);
        float4 b0 = *(const float4*)(bptr);
        float4 b1 = *(const float4*)(bptr + 4);
        As[0][akq + 0][am] = a0.x; As[0][akq + 1][am] = a0.y;
        As[0][akq + 2][am] = a0.z; As[0][akq + 3][am] = a0.w;
        As[0][akq + 4][am] = a1.x; As[0][akq + 5][am] = a1.y;
        As[0][akq + 6][am] = a1.z; As[0][akq + 7][am] = a1.w;
        *(float4*)&Bs[0][bk][bjq] = b0;
        *(float4*)&Bs[0][bk][bjq + 4] = b1;
    }
    __syncthreads();

    float acc[4][4] = {};
    const int NK = DQ / BK;  // 16
    for (int kc = 0; kc < NK; kc++) {
        const int cur = kc & 1;
        const bool more = (kc + 1 < NK);
        float4 na0, na1, nb0, nb1;
        if (more) {
            int k0 = (kc + 1) * BK;
            na0 = *(const float4*)(aptr + k0);
            na1 = *(const float4*)(aptr + k0 + 4);
            nb0 = *(const float4*)(bptr + (size_t)k0 * DQ);
            nb1 = *(const float4*)(bptr + (size_t)k0 * DQ + 4);
        }
        #pragma unroll
        for (int kk = 0; kk < BK; kk++) {
            float4 a4 = *(const float4*)&As[cur][kk][ty * 4];
            float4 b4 = *(const float4*)&Bs[cur][kk][tx * 4];
            float a[4] = {a4.x, a4.y, a4.z, a4.w};
            float bb[4] = {b4.x, b4.y, b4.z, b4.w};
            #pragma unroll
            for (int i = 0; i < 4; i++)
                #pragma unroll
                for (int j = 0; j < 4; j++) acc[i][j] += a[i] * bb[j];
        }
        if (more) {
            int nx = cur ^ 1;
            As[nx][akq + 0][am] = na0.x; As[nx][akq + 1][am] = na0.y;
            As[nx][akq + 2][am] = na0.z; As[nx][akq + 3][am] = na0.w;
            As[nx][akq + 4][am] = na1.x; As[nx][akq + 5][am] = na1.y;
            As[nx][akq + 6][am] = na1.z; As[nx][akq + 7][am] = na1.w;
            *(float4*)&Bs[nx][bk][bjq] = nb0;
            *(float4*)&Bs[nx][bk][bjq + 4] = nb1;
        }
        __syncthreads();
    }

    float* outp = sf ? g_lsk : g_lall;
    #pragma unroll
    for (int i = 0; i < 4; i++) {
        int m = ty * 4 + i;
        int b = m0 + m;
        const float* xr = s_rowp[m];
        const float* prep = sf ? (g_pre_gap + (size_t)s_gap[m] * DQ) : g_caf;
        #pragma unroll
        for (int j = 0; j < 4; j++) {
            int col = n0 + tx * 4 + j;
            float f = sigf(acc[i][j] + prep[col]);
            outp[(size_t)b * DQ + col] = xr[col] * f;
        }
    }
}

// ---------------- stage B ----------------
// nt 0..7  : h = relu([lall|lsk] @ W_o1[0:2d] + pre_o1)   -> g_h    (K=1024)
// nt 8..15 : new_all = lall + tanh(...)                   -> g_all  (K=512)
// nt 16..23: new_sk  = lsk  + tanh(...)                   -> g_rows (K=512)
__global__ void __launch_bounds__(256, 1)
k_stageB(int s, const int* __restrict__ nsk, const int* __restrict__ nans,
         const float* __restrict__ W_o1, const float* __restrict__ W_as,
         const float* __restrict__ W_ss) {
    __shared__ __align__(16) float As[2][BK][BM];
    __shared__ __align__(16) float Bs[2][BK][BN];

    const int nt = blockIdx.x, mt = blockIdx.y;
    const int region = nt >> 3;
    const int n0 = (nt & 7) * BN, m0 = mt * BM;
    const int tid = threadIdx.x;
    const int am = tid >> 2, akq = (tid & 3) * 8;
    const int bk = tid >> 3, bjq = (tid & 7) * 8;
    const int tx = tid & 15, ty = tid >> 4;

    const float* Wbase = (region == 0) ? W_o1 : (region == 1) ? W_as : W_ss;
    const float* bptr = Wbase + n0 + bk * DQ + bjq;
    const int NK = (region == 0) ? (2 * DQ / BK) : (DQ / BK);
    const float* Abase = (region == 2) ? g_lsk : g_lall;
    const size_t rowoff = (size_t)(m0 + am) * DQ + akq;

    auto aSrc = [&](int k0) -> const float* {
        if (region == 0 && k0 >= DQ) return g_lsk + rowoff + (k0 - DQ);
        return Abase + rowoff + k0;
    };

    {
        const float* ap = aSrc(0);
        float4 a0 = *(const float4*)(ap);
        float4 a1 = *(const float4*)(ap + 4);
        float4 b0 = *(const float4*)(bptr);
        float4 b1 = *(const float4*)(bptr + 4);
        As[0][akq + 0][am] = a0.x; As[0][akq + 1][am] = a0.y;
        As[0][akq + 2][am] = a0.z; As[0][akq + 3][am] = a0.w;
        As[0][akq + 4][am] = a1.x; As[0][akq + 5][am] = a1.y;
        As[0][akq + 6][am] = a1.z; As[0][akq + 7][am] = a1.w;
        *(float4*)&Bs[0][bk][bjq] = b0;
        *(float4*)&Bs[0][bk][bjq + 4] = b1;
    }
    __syncthreads();

    float acc[4][4] = {};
    for (int kc = 0; kc < NK; kc++) {
        const int cur = kc & 1;
        const bool more = (kc + 1 < NK);
        float4 na0, na1, nb0, nb1;
        if (more) {
            int k0 = (kc + 1) * BK;
            const float* ap = aSrc(k0);
            na0 = *(const float4*)(ap);
            na1 = *(const float4*)(ap + 4);
            nb0 = *(const float4*)(bptr + (size_t)k0 * DQ);
            nb1 = *(const float4*)(bptr + (size_t)k0 * DQ + 4);
        }
        #pragma unroll
        for (int kk = 0; kk < BK; kk++) {
            float4 a4 = *(const float4*)&As[cur][kk][ty * 4];
            float4 b4 = *(const float4*)&Bs[cur][kk][tx * 4];
            float a[4] = {a4.x, a4.y, a4.z, a4.w};
            float bb[4] = {b4.x, b4.y, b4.z, b4.w};
            #pragma unroll
            for (int i = 0; i < 4; i++)
                #pragma unroll
                for (int j = 0; j < 4; j++) acc[i][j] += a[i] * bb[j];
        }
        if (more) {
            int nx = cur ^ 1;
            As[nx][akq + 0][am] = na0.x; As[nx][akq + 1][am] = na0.y;
            As[nx][akq + 2][am] = na0.z; As[nx][akq + 3][am] = na0.w;
            As[nx][akq + 4][am] = na1.x; As[nx][akq + 5][am] = na1.y;
            As[nx][akq + 6][am] = na1.z; As[nx][akq + 7][am] = na1.w;
            *(float4*)&Bs[nx][bk][bjq] = nb0;
            *(float4*)&Bs[nx][bk][bjq + 4] = nb1;
        }
        __syncthreads();
    }

    #pragma unroll
    for (int i = 0; i < 4; i++) {
        int m = ty * 4 + i;
        int b = m0 + m;
        int ks = nsk[b * SQ + s];
        #pragma unroll
        for (int j = 0; j < 4; j++) {
            int col = n0 + tx * 4 + j;
            float z = acc[i][j];
            if (region == 0) {
                z += g_pre_o1[(size_t)ks * DQ + col];
                g_h[(size_t)b * DQ + col] = fmaxf(z, 0.f);
            } else if (region == 1) {
                int a = nans[b * SQ + s];
                z += g_pre_as_sk[(size_t)ks * DQ + col] + g_pre_as_an[(size_t)a * DQ + col];
                g_all[(size_t)b * DQ + col] = g_lall[(size_t)b * DQ + col] + tanhf(z);
            } else {
                int a = nans[b * SQ + s];
                z += g_pre_ss_sk[(size_t)ks * DQ + col] + g_pre_ss_an[(size_t)a * DQ + col];
                g_rows[((size_t)b * SQ + s) * DQ + col] = g_lsk[(size_t)b * DQ + col] + tanhf(z);
            }
        }
    }
}

// ---------------- stage C: output prob + last_time update ----------------
__global__ void k_stageC(int s, const int* __restrict__ nsk,
                         const float* __restrict__ W_o2, const float* __restrict__ b_o2,
                         float* __restrict__ P) {
    int warp = (blockIdx.x * blockDim.x + threadIdx.x) >> 5;  // 0..127
    int lane = threadIdx.x & 31;
    for (int b = warp; b < BQ; b += 128) {
        float acc = 0.f;
        for (int j = lane; j < DQ; j += 32) acc += g_h[b * DQ + j] * W_o2[j];
        #pragma unroll
        for (int off = 16; off; off >>= 1) acc += __shfl_xor_sync(0xffffffffu, acc, off);
        if (lane == 0) {
            P[b * SQ + s] = sigf(acc + b_o2[0]);
            g_lt[b * SKMAX + nsk[b * SQ + s]] = s;
        }
    }
}

// ---------------- launch ----------------
extern "C" void kernel_launch(void* const* d_in, const int* in_sizes, int n_in,
                              void* d_out, int out_size) {
    const int*   nsk          = (const int*)d_in[4];
    const int*   nans         = (const int*)d_in[5];
    const float* skill_embed  = (const float*)d_in[6];
    const float* ans_embed    = (const float*)d_in[7];
    const float* time_embed   = (const float*)d_in[8];
    const float* ls_state     = (const float*)d_in[9];
    const float* skill_state0 = (const float*)d_in[10];
    const float* W_sf = (const float*)d_in[11]; const float* b_sf = (const float*)d_in[12];
    const float* W_af = (const float*)d_in[13]; const float* b_af = (const float*)d_in[14];
    const float* W_ss = (const float*)d_in[15]; const float* b_ss = (const float*)d_in[16];
    const float* W_as = (const float*)d_in[17]; const float* b_as = (const float*)d_in[18];
    const float* W_o1 = (const float*)d_in[19]; const float* b_o1 = (const float*)d_in[20];
    const float* W_o2 = (const float*)d_in[21]; const float* b_o2 = (const float*)d_in[22];
    float* P = (float*)d_out;

    k_init_rows<<<dim3(SQ, BQ), 256>>>(skill_state0);
    k_init_state<<<BQ, 256>>>(ls_state);
    k_pre<<<1105, 256>>>(skill_embed, ans_embed, time_embed,
                         W_sf, b_sf, W_af, b_af, W_ss, b_ss, W_as, b_as, W_o1, b_o1);

    for (int s = 0; s < SQ; s++) {
        k_stageA<<<dim3(16, 8), 256>>>(s, nsk, W_sf, W_af);
        k_stageB<<<dim3(24, 8), 256>>>(s, nsk, nans, W_o1, W_as, W_ss);
        k_stageC<<<16, 256>>>(s, nsk, W_o2, b_o2, P);
    }
}